// round 1
// baseline (speedup 1.0000x reference)
#include <cuda_runtime.h>
#include <cstdint>

#define NB 4
#define A_TOTAL 159882
#define K_TOTAL 4507
#define NPAD 4512
#define POST_NMS 1000

__constant__ int c_lvl_n[5]    = {120000, 30000, 7500, 1875, 507};
__constant__ int c_lvl_base[5] = {0, 120000, 150000, 157500, 159375};
__constant__ int c_lvl_k[5]    = {1000, 1000, 1000, 1000, 507};

// scratch (static __device__ — no allocation)
__device__ int                d_topidx[NB * K_TOTAL];
__device__ float              d_boxes[NB * K_TOTAL * 4];
__device__ float              d_score[NB * K_TOTAL];
__device__ unsigned char      d_valid[NB * K_TOTAL];
__device__ unsigned long long d_key[NB * K_TOTAL];
__device__ unsigned short     d_order[NB * K_TOTAL];

__device__ __forceinline__ unsigned long long make_key(float f, unsigned idx) {
    unsigned u = __float_as_uint(f);
    u = (u & 0x80000000u) ? ~u : (u | 0x80000000u);
    return ((unsigned long long)u << 32) | (unsigned long long)(0xFFFFFFFFu - idx);
}

// ---------------------------------------------------------------------------
// Kernel 1: per (batch, level) exact top-k via 8-pass radix select on 64-bit
// key (value desc, index asc), then bitonic sort of winners (top_k order).
// ---------------------------------------------------------------------------
__global__ void topk_kernel(const float* __restrict__ obj) {
    int task = blockIdx.x;
    int b = task / 5, lvl = task % 5;
    int n = c_lvl_n[lvl], base = c_lvl_base[lvl], k = c_lvl_k[lvl];
    const float* v = obj + (size_t)b * A_TOTAL + base;

    __shared__ unsigned int hist[16][256];
    __shared__ unsigned long long skey[1024];
    __shared__ unsigned long long s_prefix;
    __shared__ int s_kk;
    __shared__ int s_cnt;

    int tid = threadIdx.x;
    int hcopy = (tid >> 5) & 15;

    if (tid == 0) { s_prefix = 0ULL; s_kk = k; }

    for (int d = 7; d >= 0; --d) {
        int shift = d * 8;
        for (int i = tid; i < 16 * 256; i += blockDim.x) ((unsigned*)hist)[i] = 0u;
        __syncthreads();
        unsigned long long pr = s_prefix;
        bool top = (d == 7);
        unsigned long long pmask = top ? 0ULL : ((~0ULL) << (shift + 8));
        for (int i = tid; i < n; i += blockDim.x) {
            unsigned long long key = make_key(v[i], (unsigned)i);
            if ((key & pmask) == pr)
                atomicAdd(&hist[hcopy][(unsigned)((key >> shift) & 255ULL)], 1u);
        }
        __syncthreads();
        if (tid < 256) {
            unsigned s = 0;
            #pragma unroll
            for (int c = 0; c < 16; ++c) s += hist[c][tid];
            hist[0][tid] = s;
        }
        __syncthreads();
        if (tid == 0) {
            int kk = s_kk;
            int cum = 0, bin = 255;
            for (; bin > 0; --bin) {
                int c = (int)hist[0][bin];
                if (cum + c >= kk) break;
                cum += c;
            }
            s_prefix = pr | ((unsigned long long)(unsigned)bin << shift);
            s_kk = kk - cum;
        }
        __syncthreads();
    }
    unsigned long long thresh = s_prefix;

    skey[tid] = 0ULL;
    if (tid == 0) s_cnt = 0;
    __syncthreads();
    for (int i = tid; i < n; i += blockDim.x) {
        unsigned long long key = make_key(v[i], (unsigned)i);
        if (key >= thresh) {
            int pos = atomicAdd(&s_cnt, 1);
            if (pos < 1024) skey[pos] = key;
        }
    }
    __syncthreads();

    // bitonic sort 1024, descending
    for (unsigned sz = 2; sz <= 1024; sz <<= 1) {
        for (unsigned j = sz >> 1; j > 0; j >>= 1) {
            unsigned i = tid, l = i ^ j;
            if (l > i) {
                unsigned long long a = skey[i], bb = skey[l];
                bool up = ((i & sz) == 0);
                if (up ? (a < bb) : (a > bb)) { skey[i] = bb; skey[l] = a; }
            }
            __syncthreads();
        }
    }

    if (tid < k) {
        unsigned local = 0xFFFFFFFFu - (unsigned)(skey[tid] & 0xFFFFFFFFULL);
        d_topidx[b * K_TOTAL + lvl * 1000 + tid] = base + (int)local;
    }
}

// ---------------------------------------------------------------------------
// Kernel 2: gather + decode + clip + valid + sigmoid + sort key for the
// selected 4*4507 anchors. Explicit *_rn intrinsics: no FMA contraction.
// ---------------------------------------------------------------------------
__global__ void decode_kernel(const float* __restrict__ obj,
                              const float* __restrict__ deltas,
                              const float* __restrict__ anchors) {
    int t = blockIdx.x * blockDim.x + threadIdx.x;
    if (t >= NB * K_TOTAL) return;
    int b = t / K_TOTAL;
    int p = t - b * K_TOTAL;
    int gi = d_topidx[t];

    float logit = obj[(size_t)b * A_TOTAL + gi];
    const float* dl = deltas + ((size_t)b * A_TOTAL + gi) * 4;
    const float* an = anchors + (size_t)gi * 4;

    float a0 = an[0], a1 = an[1], a2 = an[2], a3 = an[3];
    float wa = __fsub_rn(a2, a0), ha = __fsub_rn(a3, a1);
    float cxa = __fadd_rn(a0, __fmul_rn(0.5f, wa));
    float cya = __fadd_rn(a1, __fmul_rn(0.5f, ha));

    const float CLIPV = 4.135166556742356f;  // log(1000/16) rounded to f32
    float dx = dl[0], dy = dl[1];
    float dw = fminf(dl[2], CLIPV);
    float dh = fminf(dl[3], CLIPV);

    float cx = __fadd_rn(__fmul_rn(dx, wa), cxa);
    float cy = __fadd_rn(__fmul_rn(dy, ha), cya);
    float w  = __fmul_rn(expf(dw), wa);
    float h  = __fmul_rn(expf(dh), ha);

    float x1 = __fsub_rn(cx, __fmul_rn(0.5f, w));
    float y1 = __fsub_rn(cy, __fmul_rn(0.5f, h));
    float x2 = __fadd_rn(cx, __fmul_rn(0.5f, w));
    float y2 = __fadd_rn(cy, __fmul_rn(0.5f, h));

    x1 = fminf(fmaxf(x1, 0.0f), 800.0f);
    y1 = fminf(fmaxf(y1, 0.0f), 800.0f);
    x2 = fminf(fmaxf(x2, 0.0f), 800.0f);
    y2 = fminf(fmaxf(y2, 0.0f), 800.0f);

    float score = __fdiv_rn(1.0f, __fadd_rn(1.0f, expf(-logit)));
    bool valid = (__fsub_rn(x2, x1) >= 0.001f) &&
                 (__fsub_rn(y2, y1) >= 0.001f) &&
                 (score >= 0.0f);
    float ssel = valid ? score : __int_as_float(0xff800000);  // -inf

    d_boxes[(size_t)t * 4 + 0] = x1;
    d_boxes[(size_t)t * 4 + 1] = y1;
    d_boxes[(size_t)t * 4 + 2] = x2;
    d_boxes[(size_t)t * 4 + 3] = y2;
    d_score[t] = score;
    d_valid[t] = valid ? 1 : 0;
    d_key[t] = make_key(ssel, (unsigned)p);  // (score desc, pos asc) stable
}

// ---------------------------------------------------------------------------
// Kernel 3: per-image stable sort of 4507 items (pad to 8192), bitonic,
// descending by 64-bit key. One block per image, 64KB dynamic smem.
// ---------------------------------------------------------------------------
__global__ void sort_kernel() {
    int b = blockIdx.x;
    extern __shared__ unsigned long long sk[];
    int tid = threadIdx.x;
    for (int i = tid; i < 8192; i += 1024)
        sk[i] = (i < K_TOTAL) ? d_key[b * K_TOTAL + i] : 0ULL;
    __syncthreads();
    for (unsigned sz = 2; sz <= 8192; sz <<= 1) {
        for (unsigned j = sz >> 1; j > 0; j >>= 1) {
            for (int i = tid; i < 8192; i += 1024) {
                unsigned l = (unsigned)i ^ j;
                if (l > (unsigned)i) {
                    unsigned long long a = sk[i], bb = sk[l];
                    bool up = (((unsigned)i & sz) == 0);
                    if (up ? (a < bb) : (a > bb)) { sk[i] = bb; sk[l] = a; }
                }
            }
            __syncthreads();
        }
    }
    for (int r = tid; r < K_TOTAL; r += 1024)
        d_order[b * K_TOTAL + r] =
            (unsigned short)(0xFFFFFFFFu - (unsigned)(sk[r] & 0xFFFFFFFFULL));
}

// ---------------------------------------------------------------------------
// Kernel 4: greedy batched-NMS per image with early exit at 1000 kept.
// Offset boxes + areas in shared. One block per image.
// ---------------------------------------------------------------------------
#define NMS_SMEM (NPAD * 4 * 5 + NPAD * 2 + 1024 * 2 + NPAD)

__global__ void nms_kernel(float* __restrict__ out) {
    int b = blockIdx.x;
    extern __shared__ unsigned char smemraw[];
    float* s_x1 = (float*)smemraw;
    float* s_y1 = s_x1 + NPAD;
    float* s_x2 = s_y1 + NPAD;
    float* s_y2 = s_x2 + NPAD;
    float* s_ar = s_y2 + NPAD;
    unsigned short* s_pos  = (unsigned short*)(s_ar + NPAD);
    unsigned short* s_outp = s_pos + NPAD;
    unsigned char*  s_keep = (unsigned char*)(s_outp + 1024);

    int tid = threadIdx.x;

    for (int r = tid; r < K_TOTAL; r += blockDim.x) {
        int p = d_order[b * K_TOTAL + r];
        s_pos[r] = (unsigned short)p;
        int lvl = p / 1000;
        float off = (float)lvl * 1000.0f;
        const float* bx = &d_boxes[((size_t)b * K_TOTAL + p) * 4];
        float x1 = __fadd_rn(bx[0], off);
        float y1 = __fadd_rn(bx[1], off);
        float x2 = __fadd_rn(bx[2], off);
        float y2 = __fadd_rn(bx[3], off);
        s_x1[r] = x1; s_y1[r] = y1; s_x2[r] = x2; s_y2[r] = y2;
        s_ar[r] = __fmul_rn(__fsub_rn(x2, x1), __fsub_rn(y2, y1));
        s_keep[r] = d_valid[b * K_TOTAL + p];
    }
    __syncthreads();

    int count = 0;
    for (int i = 0; i < K_TOTAL; ++i) {
        if (!s_keep[i]) continue;               // uniform shared read
        if (count < POST_NMS && tid == 0) s_outp[count] = (unsigned short)i;
        ++count;
        if (count >= POST_NMS) break;           // later items can't affect ranks<1000
        float bx1 = s_x1[i], by1 = s_y1[i], bx2 = s_x2[i], by2 = s_y2[i];
        float ba = s_ar[i];
        for (int j = i + 1 + tid; j < K_TOTAL; j += blockDim.x) {
            if (!s_keep[j]) continue;
            float xx1 = fmaxf(bx1, s_x1[j]);
            float yy1 = fmaxf(by1, s_y1[j]);
            float xx2 = fminf(bx2, s_x2[j]);
            float yy2 = fminf(by2, s_y2[j]);
            float w = fmaxf(__fsub_rn(xx2, xx1), 0.0f);
            float h = fmaxf(__fsub_rn(yy2, yy1), 0.0f);
            float inter = __fmul_rn(w, h);
            float iou = __fdiv_rn(inter, __fsub_rn(__fadd_rn(ba, s_ar[j]), inter));
            if (iou > 0.7f) s_keep[j] = 0;
        }
        __syncthreads();
    }
    __syncthreads();

    int kept = count < POST_NMS ? count : POST_NMS;
    if (tid < POST_NMS) {
        float* o = out + ((size_t)b * POST_NMS + tid) * 5;
        if (tid < kept) {
            int i = s_outp[tid];
            int p = s_pos[i];
            const float* bx = &d_boxes[((size_t)b * K_TOTAL + p) * 4];
            o[0] = bx[0]; o[1] = bx[1]; o[2] = bx[2]; o[3] = bx[3];
            o[4] = d_score[b * K_TOTAL + p];
        } else {
            o[0] = 0.0f; o[1] = 0.0f; o[2] = 0.0f; o[3] = 0.0f; o[4] = 0.0f;
        }
    }
}

// ---------------------------------------------------------------------------
extern "C" void kernel_launch(void* const* d_in, const int* in_sizes, int n_in,
                              void* d_out, int out_size) {
    const float* obj     = (const float*)d_in[0];
    const float* deltas  = (const float*)d_in[1];
    const float* anchors = (const float*)d_in[2];
    float* out = (float*)d_out;

    cudaFuncSetAttribute(sort_kernel, cudaFuncAttributeMaxDynamicSharedMemorySize,
                         8192 * sizeof(unsigned long long));
    cudaFuncSetAttribute(nms_kernel, cudaFuncAttributeMaxDynamicSharedMemorySize,
                         NMS_SMEM);

    topk_kernel<<<NB * 5, 1024>>>(obj);
    decode_kernel<<<(NB * K_TOTAL + 255) / 256, 256>>>(obj, deltas, anchors);
    sort_kernel<<<NB, 1024, 8192 * sizeof(unsigned long long)>>>();
    nms_kernel<<<NB, 1024, NMS_SMEM>>>(out);
}

// round 2
// speedup vs baseline: 5.2077x; 5.2077x over previous
#include <cuda_runtime.h>
#include <cstdint>

#define NB 4
#define A_TOTAL 159882
#define K_TOTAL 4507
#define POST_NMS 1000
#define CAP 3072

__constant__ int c_lvl_n[5]    = {120000, 30000, 7500, 1875, 507};
__constant__ int c_lvl_base[5] = {0, 120000, 150000, 157500, 159375};
__constant__ int c_lvl_k[5]    = {1000, 1000, 1000, 1000, 507};

// static scratch (no allocation)
__device__ int                d_topidx[NB * K_TOTAL];
__device__ float              d_boxes[NB * K_TOTAL * 4];
__device__ float              d_score[NB * K_TOTAL];
__device__ unsigned char      d_valid[NB * K_TOTAL];
__device__ unsigned long long d_key[NB * K_TOTAL];
__device__ unsigned char      d_kept[NB * K_TOTAL];

__device__ __forceinline__ unsigned xf32(float f) {
    unsigned u = __float_as_uint(f);
    return (u & 0x80000000u) ? ~u : (u | 0x80000000u);
}

// ---------------------------------------------------------------------------
// Kernel 1: per (batch, level) exact top-k.
// One 12-bit histogram scan -> parallel suffix-scan pivot -> one selection
// scan (direct winners + pivot-bin candidates in smem) -> bitonic sorts.
// A second refinement stage handles candidate overflow (practically unused).
// ---------------------------------------------------------------------------
extern "C" __global__ void __launch_bounds__(1024)
topk2_kernel(const float* __restrict__ obj) {
    int task = blockIdx.x;
    int b = task / 5, lvl = task % 5;
    int n = c_lvl_n[lvl], base = c_lvl_base[lvl], k = c_lvl_k[lvl];
    const float* v = obj + (size_t)b * A_TOTAL + base;

    extern __shared__ unsigned char sm[];
    unsigned (*hist)[4096]    = (unsigned (*)[4096])sm;                       // 64KB
    unsigned long long* cand  = (unsigned long long*)(sm + 65536);            // 32KB (4096)
    unsigned long long* win   = (unsigned long long*)(sm + 65536 + 32768);    // 8KB  (1024)
    unsigned* swarp           = (unsigned*)(sm + 65536 + 32768 + 8192);       // 128B

    __shared__ int s_pivot, s_direct, s_nw, s_nc;

    int tid = threadIdx.x;
    int cpy = (tid >> 5) & 3;
    int lane = tid & 31, wid = tid >> 5;

    win[tid] = 0ULL;
    if (tid == 0) s_nw = 0;

    int kk = k;
    unsigned pmask = 0u, pval = 0u;
    int nc = 0;

    for (int stage = 0; stage < 2; ++stage) {
        int shift = (stage == 0) ? 20 : 8;
        for (int q = tid; q < 4 * 4096; q += 1024) ((unsigned*)hist)[q] = 0u;
        for (int q = tid; q < 4096; q += 1024) cand[q] = 0ULL;
        if (tid == 0) s_nc = 0;
        __syncthreads();

        // histogram scan
        for (int i = tid; i < n; i += 1024) {
            unsigned u = xf32(v[i]);
            if ((u & pmask) == pval)
                atomicAdd(&hist[cpy][(u >> shift) & 0xFFFu], 1u);
        }
        __syncthreads();
        for (int q = tid; q < 4096; q += 1024)
            hist[0][q] = hist[0][q] + hist[1][q] + hist[2][q] + hist[3][q];
        __syncthreads();

        // descending-order prefix sums over 4096 bins, find pivot bin
        unsigned aa[4];
        #pragma unroll
        for (int r = 0; r < 4; ++r) aa[r] = hist[0][4095 - (tid * 4 + r)];
        unsigned tsum = aa[0] + aa[1] + aa[2] + aa[3];
        unsigned inc = tsum;
        #pragma unroll
        for (int o = 1; o < 32; o <<= 1) {
            unsigned vv = __shfl_up_sync(0xffffffffu, inc, o);
            if (lane >= o) inc += vv;
        }
        if (lane == 31) swarp[wid] = inc;
        __syncthreads();
        if (wid == 0) {
            unsigned w = swarp[lane], wi = w;
            #pragma unroll
            for (int o = 1; o < 32; o <<= 1) {
                unsigned vv = __shfl_up_sync(0xffffffffu, wi, o);
                if (lane >= o) wi += vv;
            }
            swarp[lane] = wi - w;   // exclusive warp prefix
        }
        __syncthreads();
        unsigned P = swarp[wid] + (inc - tsum);   // thread-exclusive prefix
        #pragma unroll
        for (int r = 0; r < 4; ++r) {
            P += aa[r];
            if ((int)P >= kk && (int)(P - aa[r]) < kk) {
                s_pivot = 4095 - (tid * 4 + r);
                s_direct = (int)(P - aa[r]);
            }
        }
        __syncthreads();
        int pivot = s_pivot;

        // selection scan
        for (int i = tid; i < n; i += 1024) {
            unsigned u = xf32(v[i]);
            if ((u & pmask) != pval) continue;
            int bin = (int)((u >> shift) & 0xFFFu);
            unsigned long long key = ((unsigned long long)u << 32) |
                                     (unsigned long long)(0xFFFFFFFFu - (unsigned)i);
            if (bin > pivot) {
                int pos = atomicAdd(&s_nw, 1);
                win[pos] = key;
            } else if (bin == pivot) {
                int pos = atomicAdd(&s_nc, 1);
                if (pos < CAP) cand[pos] = key;
            }
        }
        __syncthreads();
        kk -= s_direct;
        nc = s_nc;
        if (nc <= CAP) break;
        pmask |= 0xFFFu << shift;
        pval  |= ((unsigned)pivot) << shift;
        __syncthreads();
    }
    if (nc > CAP) nc = CAP;

    // bitonic sort candidates (4096) desc
    for (unsigned sz = 2; sz <= 4096; sz <<= 1) {
        for (unsigned j = sz >> 1; j; j >>= 1) {
            for (int i = tid; i < 4096; i += 1024) {
                unsigned l = (unsigned)i ^ j;
                if (l > (unsigned)i) {
                    unsigned long long x = cand[i], y = cand[l];
                    bool up = ((i & sz) == 0);
                    if (up ? (x < y) : (x > y)) { cand[i] = y; cand[l] = x; }
                }
            }
            __syncthreads();
        }
    }
    int nw = s_nw;
    if (tid < kk) win[nw + tid] = cand[tid];
    __syncthreads();

    // bitonic sort winners (1024) desc -> top_k output order
    for (unsigned sz = 2; sz <= 1024; sz <<= 1) {
        for (unsigned j = sz >> 1; j; j >>= 1) {
            unsigned i = (unsigned)tid, l = i ^ j;
            if (l > i) {
                unsigned long long x = win[i], y = win[l];
                bool up = ((i & sz) == 0);
                if (up ? (x < y) : (x > y)) { win[i] = y; win[l] = x; }
            }
            __syncthreads();
        }
    }
    if (tid < k) {
        unsigned local = 0xFFFFFFFFu - (unsigned)(win[tid] & 0xFFFFFFFFULL);
        d_topidx[b * K_TOTAL + lvl * 1000 + tid] = base + (int)local;
    }
}

// ---------------------------------------------------------------------------
// Kernel 2: gather + decode + clip + valid + sigmoid + stable sort key.
// Explicit *_rn intrinsics: no FMA contraction (matches XLA).
// ---------------------------------------------------------------------------
__global__ void decode_kernel(const float* __restrict__ obj,
                              const float* __restrict__ deltas,
                              const float* __restrict__ anchors) {
    int t = blockIdx.x * blockDim.x + threadIdx.x;
    if (t >= NB * K_TOTAL) return;
    int b = t / K_TOTAL;
    int p = t - b * K_TOTAL;
    int gi = d_topidx[t];

    float logit = obj[(size_t)b * A_TOTAL + gi];
    float4 dl = *(const float4*)&deltas[((size_t)b * A_TOTAL + gi) * 4];
    float4 an = *(const float4*)&anchors[(size_t)gi * 4];

    float wa = __fsub_rn(an.z, an.x), ha = __fsub_rn(an.w, an.y);
    float cxa = __fadd_rn(an.x, __fmul_rn(0.5f, wa));
    float cya = __fadd_rn(an.y, __fmul_rn(0.5f, ha));

    const float CLIPV = 4.135166556742356f;  // log(1000/16) as f32
    float dw = fminf(dl.z, CLIPV);
    float dh = fminf(dl.w, CLIPV);

    float cx = __fadd_rn(__fmul_rn(dl.x, wa), cxa);
    float cy = __fadd_rn(__fmul_rn(dl.y, ha), cya);
    float w  = __fmul_rn(expf(dw), wa);
    float h  = __fmul_rn(expf(dh), ha);

    float x1 = __fsub_rn(cx, __fmul_rn(0.5f, w));
    float y1 = __fsub_rn(cy, __fmul_rn(0.5f, h));
    float x2 = __fadd_rn(cx, __fmul_rn(0.5f, w));
    float y2 = __fadd_rn(cy, __fmul_rn(0.5f, h));

    x1 = fminf(fmaxf(x1, 0.0f), 800.0f);
    y1 = fminf(fmaxf(y1, 0.0f), 800.0f);
    x2 = fminf(fmaxf(x2, 0.0f), 800.0f);
    y2 = fminf(fmaxf(y2, 0.0f), 800.0f);

    float score = __fdiv_rn(1.0f, __fadd_rn(1.0f, expf(-logit)));
    bool valid = (__fsub_rn(x2, x1) >= 0.001f) &&
                 (__fsub_rn(y2, y1) >= 0.001f) &&
                 (score >= 0.0f);
    float ssel = valid ? score : __int_as_float(0xff800000);  // -inf

    d_boxes[(size_t)t * 4 + 0] = x1;
    d_boxes[(size_t)t * 4 + 1] = y1;
    d_boxes[(size_t)t * 4 + 2] = x2;
    d_boxes[(size_t)t * 4 + 3] = y2;
    d_score[t] = score;
    d_valid[t] = valid ? 1 : 0;
    unsigned u = xf32(ssel);
    d_key[t] = ((unsigned long long)u << 32) |
               (unsigned long long)(0xFFFFFFFFu - (unsigned)p);
}

// ---------------------------------------------------------------------------
// Kernel 3: per (batch, level) greedy NMS. Cross-level IoU is exactly 0 by
// the offset construction, so batched-NMS decomposes per level. One j per
// thread; division replaced by an exact-safe margin test (rare fdiv path).
// ---------------------------------------------------------------------------
extern "C" __global__ void __launch_bounds__(1024)
nms_level_kernel() {
    int task = blockIdx.x;
    int b = task / 5, lvl = task % 5;
    int nl = c_lvl_k[lvl];

    __shared__ float sx1[1024], sy1[1024], sx2[1024], sy2[1024], sar[1024];
    __shared__ unsigned long long skey[1024];
    __shared__ unsigned char skeep[1024];

    int tid = threadIdx.x;
    unsigned long long key = 0ULL;
    if (tid < nl) key = d_key[b * K_TOTAL + lvl * 1000 + tid];
    skey[tid] = key;
    __syncthreads();

    // bitonic sort 1024 desc: (score desc, pos asc) == global-order restriction
    for (unsigned sz = 2; sz <= 1024; sz <<= 1) {
        for (unsigned j = sz >> 1; j; j >>= 1) {
            unsigned i = (unsigned)tid, l = i ^ j;
            if (l > i) {
                unsigned long long x = skey[i], y = skey[l];
                bool up = ((i & sz) == 0);
                if (up ? (x < y) : (x > y)) { skey[i] = y; skey[l] = x; }
            }
            __syncthreads();
        }
    }
    key = skey[tid];

    int p = -1;
    unsigned char kp = 0;
    float x1 = 0.f, y1 = 0.f, x2 = 0.f, y2 = 0.f, ar = 0.f;
    if (key != 0ULL) {
        p = (int)(0xFFFFFFFFu - (unsigned)(key & 0xFFFFFFFFULL));
        float4 bx = *(const float4*)&d_boxes[((size_t)b * K_TOTAL + p) * 4];
        float off = (float)lvl * 1000.0f;
        x1 = __fadd_rn(bx.x, off);
        y1 = __fadd_rn(bx.y, off);
        x2 = __fadd_rn(bx.z, off);
        y2 = __fadd_rn(bx.w, off);
        ar = __fmul_rn(__fsub_rn(x2, x1), __fsub_rn(y2, y1));
        kp = d_valid[b * K_TOTAL + p];
    }
    sx1[tid] = x1; sy1[tid] = y1; sx2[tid] = x2; sy2[tid] = y2; sar[tid] = ar;
    skeep[tid] = kp;
    __syncthreads();

    bool alive = (kp != 0);
    for (int i = 0; i < nl; ++i) {
        if (!skeep[i]) continue;
        float bx1 = sx1[i], by1 = sy1[i], bx2 = sx2[i], by2 = sy2[i], ba = sar[i];
        if (tid > i && alive) {
            float xx1 = fmaxf(bx1, x1);
            float yy1 = fmaxf(by1, y1);
            float xx2 = fminf(bx2, x2);
            float yy2 = fminf(by2, y2);
            float w = fmaxf(__fsub_rn(xx2, xx1), 0.0f);
            float h = fmaxf(__fsub_rn(yy2, yy1), 0.0f);
            float inter = __fmul_rn(w, h);
            float uni = __fsub_rn(__fadd_rn(ba, ar), inter);
            float r = __fmaf_rn(-0.7f, uni, inter);
            float m = __fmul_rn(uni, 3.0e-7f);
            bool sup;
            if (fabsf(r) > m) sup = (r > 0.0f);                     // certain
            else sup = (__fdiv_rn(inter, uni) > 0.7f);              // exact, rare
            if (sup) { alive = false; skeep[tid] = 0; }
        }
        __syncthreads();
    }
    if (p >= 0) d_kept[b * K_TOTAL + p] = skeep[tid];
}

// ---------------------------------------------------------------------------
// Kernel 4: per image, merge kept items across levels by global key order,
// take top-1000, write output rows; rest zero.
// ---------------------------------------------------------------------------
extern "C" __global__ void __launch_bounds__(1024)
merge_kernel(float* __restrict__ out) {
    int b = blockIdx.x;
    extern __shared__ unsigned long long sk[];
    int tid = threadIdx.x;
    for (int i = tid; i < 8192; i += 1024) {
        unsigned long long key = 0ULL;
        if (i < K_TOTAL && d_kept[b * K_TOTAL + i])
            key = d_key[b * K_TOTAL + i];
        sk[i] = key;
    }
    __syncthreads();
    for (unsigned sz = 2; sz <= 8192; sz <<= 1) {
        for (unsigned j = sz >> 1; j; j >>= 1) {
            for (int i = tid; i < 8192; i += 1024) {
                unsigned l = (unsigned)i ^ j;
                if (l > (unsigned)i) {
                    unsigned long long x = sk[i], y = sk[l];
                    bool up = ((i & sz) == 0);
                    if (up ? (x < y) : (x > y)) { sk[i] = y; sk[l] = x; }
                }
            }
            __syncthreads();
        }
    }
    if (tid < POST_NMS) {
        unsigned long long key = sk[tid];
        float* o = out + ((size_t)b * POST_NMS + tid) * 5;
        if (key != 0ULL) {
            int p = (int)(0xFFFFFFFFu - (unsigned)(key & 0xFFFFFFFFULL));
            float4 bx = *(const float4*)&d_boxes[((size_t)b * K_TOTAL + p) * 4];
            o[0] = bx.x; o[1] = bx.y; o[2] = bx.z; o[3] = bx.w;
            o[4] = d_score[b * K_TOTAL + p];
        } else {
            o[0] = 0.f; o[1] = 0.f; o[2] = 0.f; o[3] = 0.f; o[4] = 0.f;
        }
    }
}

// ---------------------------------------------------------------------------
extern "C" void kernel_launch(void* const* d_in, const int* in_sizes, int n_in,
                              void* d_out, int out_size) {
    const float* obj     = (const float*)d_in[0];
    const float* deltas  = (const float*)d_in[1];
    const float* anchors = (const float*)d_in[2];
    float* out = (float*)d_out;

    const int TOPK_SMEM = 65536 + 32768 + 8192 + 128;
    cudaFuncSetAttribute(topk2_kernel, cudaFuncAttributeMaxDynamicSharedMemorySize,
                         TOPK_SMEM);
    cudaFuncSetAttribute(merge_kernel, cudaFuncAttributeMaxDynamicSharedMemorySize,
                         8192 * (int)sizeof(unsigned long long));

    topk2_kernel<<<NB * 5, 1024, TOPK_SMEM>>>(obj);
    decode_kernel<<<(NB * K_TOTAL + 255) / 256, 256>>>(obj, deltas, anchors);
    nms_level_kernel<<<NB * 5, 1024>>>();
    merge_kernel<<<NB, 1024, 8192 * sizeof(unsigned long long)>>>(out);
}

// round 3
// speedup vs baseline: 10.5514x; 2.0261x over previous
#include <cuda_runtime.h>
#include <cstdint>

#define NB 4
#define A_TOTAL 159882
#define K_TOTAL 4507
#define POST_NMS 1000
#define CAP 3072
#define NTASK (NB * 5)

__constant__ int c_lvl_n[5]    = {120000, 30000, 7500, 1875, 507};
__constant__ int c_lvl_base[5] = {0, 120000, 150000, 157500, 159375};
__constant__ int c_lvl_k[5]    = {1000, 1000, 1000, 1000, 507};

// static scratch (no allocation)
__device__ int                d_topidx[NB * K_TOTAL];
__device__ float              d_boxes[NB * K_TOTAL * 4];
__device__ float              d_score[NB * K_TOTAL];
__device__ unsigned char      d_valid[NB * K_TOTAL];
__device__ unsigned long long d_key[NB * K_TOTAL];

__device__ float4             d_sbx[NTASK * 1024];     // sorted offset boxes
__device__ float              d_sar[NTASK * 1024];     // sorted areas
__device__ unsigned long long d_skey[NTASK * 1024];    // sorted keys
__device__ unsigned           d_valmask[NTASK * 32];   // valid bits (sorted order)
__device__ unsigned           d_sup[NTASK * 1024 * 32];// suppression bit-matrix
__device__ unsigned long long d_lvl_keys[NTASK * 1024];// kept keys, sorted desc
__device__ int                d_lvl_cnt[NTASK];

__device__ __forceinline__ unsigned xf32(float f) {
    unsigned u = __float_as_uint(f);
    return (u & 0x80000000u) ? ~u : (u | 0x80000000u);
}

// ---------------------------------------------------------------------------
// Kernel 1: per (batch, level) exact top-k (12-bit histogram select).
// ---------------------------------------------------------------------------
extern "C" __global__ void __launch_bounds__(1024)
topk2_kernel(const float* __restrict__ obj) {
    int task = blockIdx.x;
    int b = task / 5, lvl = task % 5;
    int n = c_lvl_n[lvl], base = c_lvl_base[lvl], k = c_lvl_k[lvl];
    const float* v = obj + (size_t)b * A_TOTAL + base;

    extern __shared__ unsigned char sm[];
    unsigned (*hist)[4096]    = (unsigned (*)[4096])sm;                       // 64KB
    unsigned long long* cand  = (unsigned long long*)(sm + 65536);            // 32KB
    unsigned long long* win   = (unsigned long long*)(sm + 65536 + 32768);    // 8KB
    unsigned* swarp           = (unsigned*)(sm + 65536 + 32768 + 8192);       // 128B

    __shared__ int s_pivot, s_direct, s_nw, s_nc;

    int tid = threadIdx.x;
    int cpy = (tid >> 5) & 3;
    int lane = tid & 31, wid = tid >> 5;

    win[tid] = 0ULL;
    if (tid == 0) s_nw = 0;

    int kk = k;
    unsigned pmask = 0u, pval = 0u;
    int nc = 0;

    for (int stage = 0; stage < 2; ++stage) {
        int shift = (stage == 0) ? 20 : 8;
        for (int q = tid; q < 4 * 4096; q += 1024) ((unsigned*)hist)[q] = 0u;
        for (int q = tid; q < 4096; q += 1024) cand[q] = 0ULL;
        if (tid == 0) s_nc = 0;
        __syncthreads();

        for (int i = tid; i < n; i += 1024) {
            unsigned u = xf32(v[i]);
            if ((u & pmask) == pval)
                atomicAdd(&hist[cpy][(u >> shift) & 0xFFFu], 1u);
        }
        __syncthreads();
        for (int q = tid; q < 4096; q += 1024)
            hist[0][q] = hist[0][q] + hist[1][q] + hist[2][q] + hist[3][q];
        __syncthreads();

        unsigned aa[4];
        #pragma unroll
        for (int r = 0; r < 4; ++r) aa[r] = hist[0][4095 - (tid * 4 + r)];
        unsigned tsum = aa[0] + aa[1] + aa[2] + aa[3];
        unsigned inc = tsum;
        #pragma unroll
        for (int o = 1; o < 32; o <<= 1) {
            unsigned vv = __shfl_up_sync(0xffffffffu, inc, o);
            if (lane >= o) inc += vv;
        }
        if (lane == 31) swarp[wid] = inc;
        __syncthreads();
        if (wid == 0) {
            unsigned w = swarp[lane], wi = w;
            #pragma unroll
            for (int o = 1; o < 32; o <<= 1) {
                unsigned vv = __shfl_up_sync(0xffffffffu, wi, o);
                if (lane >= o) wi += vv;
            }
            swarp[lane] = wi - w;
        }
        __syncthreads();
        unsigned P = swarp[wid] + (inc - tsum);
        #pragma unroll
        for (int r = 0; r < 4; ++r) {
            P += aa[r];
            if ((int)P >= kk && (int)(P - aa[r]) < kk) {
                s_pivot = 4095 - (tid * 4 + r);
                s_direct = (int)(P - aa[r]);
            }
        }
        __syncthreads();
        int pivot = s_pivot;

        for (int i = tid; i < n; i += 1024) {
            unsigned u = xf32(v[i]);
            if ((u & pmask) != pval) continue;
            int bin = (int)((u >> shift) & 0xFFFu);
            unsigned long long key = ((unsigned long long)u << 32) |
                                     (unsigned long long)(0xFFFFFFFFu - (unsigned)i);
            if (bin > pivot) {
                int pos = atomicAdd(&s_nw, 1);
                win[pos] = key;
            } else if (bin == pivot) {
                int pos = atomicAdd(&s_nc, 1);
                if (pos < CAP) cand[pos] = key;
            }
        }
        __syncthreads();
        kk -= s_direct;
        nc = s_nc;
        if (nc <= CAP) break;
        pmask |= 0xFFFu << shift;
        pval  |= ((unsigned)pivot) << shift;
        __syncthreads();
    }

    for (unsigned sz = 2; sz <= 4096; sz <<= 1) {
        for (unsigned j = sz >> 1; j; j >>= 1) {
            for (int i = tid; i < 4096; i += 1024) {
                unsigned l = (unsigned)i ^ j;
                if (l > (unsigned)i) {
                    unsigned long long x = cand[i], y = cand[l];
                    bool up = ((i & sz) == 0);
                    if (up ? (x < y) : (x > y)) { cand[i] = y; cand[l] = x; }
                }
            }
            __syncthreads();
        }
    }
    int nw = s_nw;
    if (tid < kk) win[nw + tid] = cand[tid];
    __syncthreads();

    for (unsigned sz = 2; sz <= 1024; sz <<= 1) {
        for (unsigned j = sz >> 1; j; j >>= 1) {
            unsigned i = (unsigned)tid, l = i ^ j;
            if (l > i) {
                unsigned long long x = win[i], y = win[l];
                bool up = ((i & sz) == 0);
                if (up ? (x < y) : (x > y)) { win[i] = y; win[l] = x; }
            }
            __syncthreads();
        }
    }
    if (tid < k) {
        unsigned local = 0xFFFFFFFFu - (unsigned)(win[tid] & 0xFFFFFFFFULL);
        d_topidx[b * K_TOTAL + lvl * 1000 + tid] = base + (int)local;
    }
}

// ---------------------------------------------------------------------------
// Kernel 2: gather + decode + clip + valid + sigmoid + stable key.
// ---------------------------------------------------------------------------
__global__ void decode_kernel(const float* __restrict__ obj,
                              const float* __restrict__ deltas,
                              const float* __restrict__ anchors) {
    int t = blockIdx.x * blockDim.x + threadIdx.x;
    if (t >= NB * K_TOTAL) return;
    int b = t / K_TOTAL;
    int p = t - b * K_TOTAL;
    int gi = d_topidx[t];

    float logit = obj[(size_t)b * A_TOTAL + gi];
    float4 dl = *(const float4*)&deltas[((size_t)b * A_TOTAL + gi) * 4];
    float4 an = *(const float4*)&anchors[(size_t)gi * 4];

    float wa = __fsub_rn(an.z, an.x), ha = __fsub_rn(an.w, an.y);
    float cxa = __fadd_rn(an.x, __fmul_rn(0.5f, wa));
    float cya = __fadd_rn(an.y, __fmul_rn(0.5f, ha));

    const float CLIPV = 4.135166556742356f;
    float dw = fminf(dl.z, CLIPV);
    float dh = fminf(dl.w, CLIPV);

    float cx = __fadd_rn(__fmul_rn(dl.x, wa), cxa);
    float cy = __fadd_rn(__fmul_rn(dl.y, ha), cya);
    float w  = __fmul_rn(expf(dw), wa);
    float h  = __fmul_rn(expf(dh), ha);

    float x1 = __fsub_rn(cx, __fmul_rn(0.5f, w));
    float y1 = __fsub_rn(cy, __fmul_rn(0.5f, h));
    float x2 = __fadd_rn(cx, __fmul_rn(0.5f, w));
    float y2 = __fadd_rn(cy, __fmul_rn(0.5f, h));

    x1 = fminf(fmaxf(x1, 0.0f), 800.0f);
    y1 = fminf(fmaxf(y1, 0.0f), 800.0f);
    x2 = fminf(fmaxf(x2, 0.0f), 800.0f);
    y2 = fminf(fmaxf(y2, 0.0f), 800.0f);

    float score = __fdiv_rn(1.0f, __fadd_rn(1.0f, expf(-logit)));
    bool valid = (__fsub_rn(x2, x1) >= 0.001f) &&
                 (__fsub_rn(y2, y1) >= 0.001f) &&
                 (score >= 0.0f);
    float ssel = valid ? score : __int_as_float(0xff800000);

    d_boxes[(size_t)t * 4 + 0] = x1;
    d_boxes[(size_t)t * 4 + 1] = y1;
    d_boxes[(size_t)t * 4 + 2] = x2;
    d_boxes[(size_t)t * 4 + 3] = y2;
    d_score[t] = score;
    d_valid[t] = valid ? 1 : 0;
    unsigned u = xf32(ssel);
    d_key[t] = ((unsigned long long)u << 32) |
               (unsigned long long)(0xFFFFFFFFu - (unsigned)p);
}

// ---------------------------------------------------------------------------
// Kernel 3: per (batch, level) sort keys desc; emit sorted offset boxes,
// areas, keys and the valid bitmask.
// ---------------------------------------------------------------------------
extern "C" __global__ void __launch_bounds__(1024)
sortlvl_kernel() {
    int task = blockIdx.x;
    int b = task / 5, lvl = task % 5;
    int nl = c_lvl_k[lvl];
    __shared__ unsigned long long skey[1024];

    int tid = threadIdx.x;
    int lane = tid & 31, wid = tid >> 5;

    unsigned long long key = 0ULL;
    if (tid < nl) key = d_key[b * K_TOTAL + lvl * 1000 + tid];
    skey[tid] = key;
    __syncthreads();

    for (unsigned sz = 2; sz <= 1024; sz <<= 1) {
        for (unsigned j = sz >> 1; j; j >>= 1) {
            unsigned i = (unsigned)tid, l = i ^ j;
            if (l > i) {
                unsigned long long x = skey[i], y = skey[l];
                bool up = ((i & sz) == 0);
                if (up ? (x < y) : (x > y)) { skey[i] = y; skey[l] = x; }
            }
            __syncthreads();
        }
    }
    key = skey[tid];

    float4 ob = make_float4(0.f, 0.f, 0.f, 0.f);
    float ar = 0.f;
    unsigned char kp = 0;
    if (key != 0ULL) {
        int p = (int)(0xFFFFFFFFu - (unsigned)(key & 0xFFFFFFFFULL));
        float4 bx = *(const float4*)&d_boxes[((size_t)b * K_TOTAL + p) * 4];
        float off = (float)lvl * 1000.0f;
        ob.x = __fadd_rn(bx.x, off);
        ob.y = __fadd_rn(bx.y, off);
        ob.z = __fadd_rn(bx.z, off);
        ob.w = __fadd_rn(bx.w, off);
        ar = __fmul_rn(__fsub_rn(ob.z, ob.x), __fsub_rn(ob.w, ob.y));
        kp = d_valid[b * K_TOTAL + p];
    }
    d_sbx[task * 1024 + tid] = ob;
    d_sar[task * 1024 + tid] = ar;
    d_skey[task * 1024 + tid] = key;
    unsigned bal = __ballot_sync(0xffffffffu, kp != 0);
    if (lane == 0) d_valmask[task * 32 + wid] = bal;
}

// ---------------------------------------------------------------------------
// Kernel 4: suppression bit-matrix. grid (8 i-chunks, 20 tasks), 1024 thr.
// Warp J covers j = 32J..32J+31; per i one ballot word, no atomics.
// ---------------------------------------------------------------------------
extern "C" __global__ void __launch_bounds__(1024)
supmask_kernel() {
    int chunk = blockIdx.x;     // i-chunk of 128
    int task  = blockIdx.y;
    int tid = threadIdx.x;
    int lane = tid & 31, J = tid >> 5;
    int j = tid;

    __shared__ float4 s_bx[128];
    __shared__ float  s_ar[128];
    if (tid < 128) {
        s_bx[tid] = d_sbx[task * 1024 + chunk * 128 + tid];
        s_ar[tid] = d_sar[task * 1024 + chunk * 128 + tid];
    }
    __syncthreads();

    float4 bj = d_sbx[task * 1024 + j];
    float arj = d_sar[task * 1024 + j];

    for (int ii = 0; ii < 128; ++ii) {
        int i = chunk * 128 + ii;
        float4 bi = s_bx[ii];
        float ai = s_ar[ii];
        bool sup = false;
        if (j > i) {
            float xx1 = fmaxf(bi.x, bj.x);
            float yy1 = fmaxf(bi.y, bj.y);
            float xx2 = fminf(bi.z, bj.z);
            float yy2 = fminf(bi.w, bj.w);
            float w = fmaxf(__fsub_rn(xx2, xx1), 0.0f);
            float h = fmaxf(__fsub_rn(yy2, yy1), 0.0f);
            float inter = __fmul_rn(w, h);
            float uni = __fsub_rn(__fadd_rn(ai, arj), inter);
            float r = __fmaf_rn(-0.7f, uni, inter);
            float m = __fmul_rn(uni, 3.0e-7f);
            if (fabsf(r) > m) sup = (r > 0.0f);
            else sup = (__fdiv_rn(inter, uni) > 0.7f);
        }
        unsigned bal = __ballot_sync(0xffffffffu, sup);
        if (lane == 0) d_sup[(task * 1024 + i) * 32 + J] = bal;
    }
}

// ---------------------------------------------------------------------------
// Kernel 5: warp-serial greedy walk over the bitmask (chunked, register
// resolution) + compaction of kept keys per level.
// ---------------------------------------------------------------------------
extern "C" __global__ void __launch_bounds__(1024)
walk_kernel() {
    int task = blockIdx.x;
    extern __shared__ unsigned s_sup[];   // [1024][32]
    __shared__ unsigned s_aw[32];
    __shared__ int s_wsum[32], s_wbase[32];

    int tid = threadIdx.x;
    int lane = tid & 31, wid = tid >> 5;

    for (int q = tid; q < 32768; q += 1024)
        s_sup[q] = d_sup[task * 32768 + q];
    __syncthreads();

    if (wid == 0) {
        unsigned alive = d_valmask[task * 32 + lane];
        #pragma unroll 1
        for (int c = 0; c < 32; ++c) {
            unsigned a = __shfl_sync(0xffffffffu, alive, c);
            if (a) {
                unsigned w[32];
                #pragma unroll
                for (int t = 0; t < 32; ++t)
                    w[t] = s_sup[(c * 32 + t) * 32 + c];
                #pragma unroll
                for (int t = 0; t < 32; ++t)
                    if (a & (1u << t)) a &= ~w[t];
                #pragma unroll
                for (int t = 0; t < 32; ++t)
                    if ((a >> t) & 1u) alive &= ~s_sup[(c * 32 + t) * 32 + lane];
            }
            if (lane == c) alive = a;
        }
        s_aw[lane] = alive;
    }
    __syncthreads();

    bool keep = (s_aw[wid] >> lane) & 1u;
    unsigned bal = __ballot_sync(0xffffffffu, keep);
    if (lane == 0) s_wsum[wid] = __popc(bal);
    __syncthreads();
    if (tid == 0) {
        int s = 0;
        for (int w2 = 0; w2 < 32; ++w2) { s_wbase[w2] = s; s += s_wsum[w2]; }
        d_lvl_cnt[task] = s;
    }
    __syncthreads();
    if (keep) {
        int slot = s_wbase[wid] + __popc(bal & ((1u << lane) - 1u));
        d_lvl_keys[task * 1024 + slot] = d_skey[task * 1024 + tid];
    }
}

// ---------------------------------------------------------------------------
// Kernel 6: per image, rank kept items by binary search across the 5 sorted
// level lists; write top-1000 rows, zero the rest.
// ---------------------------------------------------------------------------
extern "C" __global__ void __launch_bounds__(1024)
merge_kernel(float* __restrict__ out) {
    int b = blockIdx.x;
    __shared__ unsigned long long s_keys[5][1024];
    __shared__ int s_cnt[5];

    int tid = threadIdx.x;
    if (tid < 5) s_cnt[tid] = d_lvl_cnt[b * 5 + tid];
    __syncthreads();

    for (int i = tid; i < 5 * 1024; i += 1024) {
        int lvl = i >> 10, r = i & 1023;
        if (r < s_cnt[lvl])
            s_keys[lvl][r] = d_lvl_keys[(b * 5 + lvl) * 1024 + r];
    }
    __syncthreads();

    int total = s_cnt[0] + s_cnt[1] + s_cnt[2] + s_cnt[3] + s_cnt[4];

    for (int i = tid; i < 5 * 1024; i += 1024) {
        int lvl = i >> 10, r = i & 1023;
        if (r >= s_cnt[lvl]) continue;
        unsigned long long key = s_keys[lvl][r];
        int rank = r;
        #pragma unroll
        for (int o = 0; o < 5; ++o) {
            if (o == lvl) continue;
            int lo = 0, hi = s_cnt[o];
            while (lo < hi) {
                int mid = (lo + hi) >> 1;
                if (s_keys[o][mid] > key) lo = mid + 1; else hi = mid;
            }
            rank += lo;
        }
        if (rank < POST_NMS) {
            int p = (int)(0xFFFFFFFFu - (unsigned)(key & 0xFFFFFFFFULL));
            float4 bx = *(const float4*)&d_boxes[((size_t)b * K_TOTAL + p) * 4];
            float* o2 = out + ((size_t)b * POST_NMS + rank) * 5;
            o2[0] = bx.x; o2[1] = bx.y; o2[2] = bx.z; o2[3] = bx.w;
            o2[4] = d_score[b * K_TOTAL + p];
        }
    }
    if (tid < POST_NMS && tid >= total) {
        float* o2 = out + ((size_t)b * POST_NMS + tid) * 5;
        o2[0] = 0.f; o2[1] = 0.f; o2[2] = 0.f; o2[3] = 0.f; o2[4] = 0.f;
    }
}

// ---------------------------------------------------------------------------
extern "C" void kernel_launch(void* const* d_in, const int* in_sizes, int n_in,
                              void* d_out, int out_size) {
    const float* obj     = (const float*)d_in[0];
    const float* deltas  = (const float*)d_in[1];
    const float* anchors = (const float*)d_in[2];
    float* out = (float*)d_out;

    const int TOPK_SMEM = 65536 + 32768 + 8192 + 128;
    cudaFuncSetAttribute(topk2_kernel, cudaFuncAttributeMaxDynamicSharedMemorySize,
                         TOPK_SMEM);
    cudaFuncSetAttribute(walk_kernel, cudaFuncAttributeMaxDynamicSharedMemorySize,
                         131072);

    topk2_kernel<<<NTASK, 1024, TOPK_SMEM>>>(obj);
    decode_kernel<<<(NB * K_TOTAL + 255) / 256, 256>>>(obj, deltas, anchors);
    sortlvl_kernel<<<NTASK, 1024>>>();
    supmask_kernel<<<dim3(8, NTASK), 1024>>>();
    walk_kernel<<<NTASK, 1024, 131072>>>();
    merge_kernel<<<NB, 1024>>>(out);
}

// round 4
// speedup vs baseline: 18.2440x; 1.7291x over previous
#include <cuda_runtime.h>
#include <cstdint>

#define NB 4
#define A_TOTAL 159882
#define K_TOTAL 4507
#define POST_NMS 1000
#define NTASK (NB * 5)
#define HB 16384            // 14-bit histogram bins
#define HSHIFT 18
#define CCAP 4096

__constant__ int c_lvl_n[5]    = {120000, 30000, 7500, 1875, 507};
__constant__ int c_lvl_base[5] = {0, 120000, 150000, 157500, 159375};
__constant__ int c_lvl_k[5]    = {1000, 1000, 1000, 1000, 507};

// supmask triangular tile table: (jc: j-block of 256, ic: i-block of 64),
// tile present iff ic <= 4*jc+3  -> 40 tiles
__constant__ unsigned char c_tile_jc[40] = {
    0,0,0,0, 1,1,1,1,1,1,1,1, 2,2,2,2,2,2,2,2,2,2,2,2,
    3,3,3,3,3,3,3,3,3,3,3,3,3,3,3,3};
__constant__ unsigned char c_tile_ic[40] = {
    0,1,2,3, 0,1,2,3,4,5,6,7, 0,1,2,3,4,5,6,7,8,9,10,11,
    0,1,2,3,4,5,6,7,8,9,10,11,12,13,14,15};

// static scratch (no allocation)
__device__ unsigned           d_hist[NTASK * HB];
__device__ int                d_cnt[2 * NTASK];      // [t]=win, [20+t]=cand
__device__ int                d_pivot[NTASK];
__device__ int                d_direct[NTASK];
__device__ unsigned long long d_win[NTASK * 1024];
__device__ unsigned long long d_cand[NTASK * CCAP];
__device__ int                d_topidx[NB * K_TOTAL];
__device__ float              d_boxes[NB * K_TOTAL * 4];
__device__ float              d_score[NB * K_TOTAL];

__device__ float4             d_sbx[NTASK * 1024];
__device__ float              d_sar[NTASK * 1024];
__device__ unsigned long long d_skey[NTASK * 1024];
__device__ unsigned           d_valmask[NTASK * 32];
__device__ unsigned           d_sup[NTASK * 1024 * 32];
__device__ unsigned long long d_lvl_keys[NTASK * 1024];
__device__ int                d_lvl_cnt[NTASK];

__device__ __forceinline__ unsigned xf32(float f) {
    unsigned u = __float_as_uint(f);
    return (u & 0x80000000u) ? ~u : (u | 0x80000000u);
}

// ---------------------------------------------------------------------------
// K0: zero histogram + counters
// ---------------------------------------------------------------------------
extern "C" __global__ void zero_kernel() {
    int i = blockIdx.x * 1024 + threadIdx.x;
    if (i < NTASK * HB) d_hist[i] = 0u;
    if (i < 2 * NTASK) d_cnt[i] = 0;
}

// ---------------------------------------------------------------------------
// K1: smem-aggregated 14-bit histogram. grid (8 slices, 20 tasks).
// ---------------------------------------------------------------------------
extern "C" __global__ void __launch_bounds__(1024)
hist_kernel(const float* __restrict__ obj) {
    int task = blockIdx.y;
    int b = task / 5, lvl = task % 5;
    int n = c_lvl_n[lvl], base = c_lvl_base[lvl];
    int chunk = (n + 7) / 8;
    int s0 = blockIdx.x * chunk;
    if (s0 >= n) return;
    int s1 = min(n, s0 + chunk);
    const float* v = obj + (size_t)b * A_TOTAL + base;

    extern __shared__ unsigned sh[];
    int tid = threadIdx.x;
    for (int q = tid; q < HB; q += 1024) sh[q] = 0u;
    __syncthreads();
    for (int i = s0 + tid; i < s1; i += 1024)
        atomicAdd(&sh[xf32(v[i]) >> HSHIFT], 1u);
    __syncthreads();
    for (int q = tid; q < HB; q += 1024) {
        unsigned c = sh[q];
        if (c) atomicAdd(&d_hist[task * HB + q], c);
    }
}

// ---------------------------------------------------------------------------
// K2: pivot find per task (20 blocks). Descending suffix scan over 16384 bins.
// ---------------------------------------------------------------------------
extern "C" __global__ void __launch_bounds__(1024)
pivot_kernel() {
    int task = blockIdx.x;
    int lvl = task % 5, k = c_lvl_k[lvl];
    __shared__ unsigned s_warp[32];
    int tid = threadIdx.x, lane = tid & 31, wid = tid >> 5;

    unsigned cnt[16], tsum = 0;
    #pragma unroll
    for (int r = 0; r < 16; ++r) {
        cnt[r] = d_hist[task * HB + (HB - 1 - (tid * 16 + r))];
        tsum += cnt[r];
    }
    unsigned inc = tsum;
    #pragma unroll
    for (int o = 1; o < 32; o <<= 1) {
        unsigned vv = __shfl_up_sync(0xffffffffu, inc, o);
        if (lane >= o) inc += vv;
    }
    if (lane == 31) s_warp[wid] = inc;
    __syncthreads();
    if (wid == 0) {
        unsigned w = (lane < 32) ? s_warp[lane] : 0, wi = w;
        #pragma unroll
        for (int o = 1; o < 32; o <<= 1) {
            unsigned vv = __shfl_up_sync(0xffffffffu, wi, o);
            if (lane >= o) wi += vv;
        }
        s_warp[lane] = wi - w;
    }
    __syncthreads();
    unsigned P = s_warp[wid] + (inc - tsum);
    #pragma unroll
    for (int r = 0; r < 16; ++r) {
        P += cnt[r];
        if ((int)P >= k && (int)(P - cnt[r]) < k) {
            d_pivot[task] = HB - 1 - (tid * 16 + r);
            d_direct[task] = (int)(P - cnt[r]);
        }
    }
}

// ---------------------------------------------------------------------------
// K3: selection scan (wide). Compact winners / pivot-bin candidates.
// ---------------------------------------------------------------------------
extern "C" __global__ void __launch_bounds__(1024)
select_kernel(const float* __restrict__ obj) {
    int task = blockIdx.y;
    int b = task / 5, lvl = task % 5;
    int n = c_lvl_n[lvl], base = c_lvl_base[lvl];
    int chunk = (n + 7) / 8;
    int s0 = blockIdx.x * chunk;
    if (s0 >= n) return;
    int s1 = min(n, s0 + chunk);
    const float* v = obj + (size_t)b * A_TOTAL + base;
    int pivot = d_pivot[task];

    for (int i = s0 + threadIdx.x; i < s1; i += 1024) {
        unsigned u = xf32(v[i]);
        int bin = (int)(u >> HSHIFT);
        if (bin < pivot) continue;
        unsigned long long key = ((unsigned long long)u << 32) |
                                 (unsigned long long)(0xFFFFFFFFu - (unsigned)i);
        if (bin > pivot) {
            int pos = atomicAdd(&d_cnt[task], 1);
            d_win[task * 1024 + pos] = key;
        } else {
            int pos = atomicAdd(&d_cnt[NTASK + task], 1);
            if (pos < CCAP) d_cand[task * CCAP + pos] = key;
        }
    }
}

// ---------------------------------------------------------------------------
// K4: per task: sort candidates (dynamic pow2 size), append, sort winners,
// emit topidx in exact top_k order.
// ---------------------------------------------------------------------------
extern "C" __global__ void __launch_bounds__(1024)
sortk_kernel() {
    int task = blockIdx.x;
    int b = task / 5, lvl = task % 5;
    int base = c_lvl_base[lvl], k = c_lvl_k[lvl];
    __shared__ unsigned long long s_cand[CCAP];
    __shared__ unsigned long long s_win[1024];

    int tid = threadIdx.x;
    int nc = min(d_cnt[NTASK + task], CCAP);
    int direct = d_direct[task];
    int kkrem = k - direct;

    int need = max(nc, kkrem);
    int S = 32; while (S < need) S <<= 1;

    for (int i = tid; i < S; i += 1024)
        s_cand[i] = (i < nc) ? d_cand[task * CCAP + i] : 0ULL;
    __syncthreads();
    for (unsigned sz = 2; sz <= (unsigned)S; sz <<= 1) {
        for (unsigned j = sz >> 1; j; j >>= 1) {
            for (int i = tid; i < S; i += 1024) {
                unsigned l = (unsigned)i ^ j;
                if (l > (unsigned)i && l < (unsigned)S) {
                    unsigned long long x = s_cand[i], y = s_cand[l];
                    bool up = ((i & sz) == 0);
                    if (up ? (x < y) : (x > y)) { s_cand[i] = y; s_cand[l] = x; }
                }
            }
            __syncthreads();
        }
    }
    unsigned long long w = 0ULL;
    if (tid < direct) w = d_win[task * 1024 + tid];
    else if (tid < k) w = s_cand[tid - direct];
    s_win[tid] = w;
    __syncthreads();
    for (unsigned sz = 2; sz <= 1024; sz <<= 1) {
        for (unsigned j = sz >> 1; j; j >>= 1) {
            unsigned i = (unsigned)tid, l = i ^ j;
            if (l > i) {
                unsigned long long x = s_win[i], y = s_win[l];
                bool up = ((i & sz) == 0);
                if (up ? (x < y) : (x > y)) { s_win[i] = y; s_win[l] = x; }
            }
            __syncthreads();
        }
    }
    if (tid < k) {
        unsigned local = 0xFFFFFFFFu - (unsigned)(s_win[tid] & 0xFFFFFFFFULL);
        d_topidx[b * K_TOTAL + lvl * 1000 + tid] = base + (int)local;
    }
}

// ---------------------------------------------------------------------------
// K5: fused decode + per-level sort. 20 blocks.
// ---------------------------------------------------------------------------
extern "C" __global__ void __launch_bounds__(1024)
decode_sort_kernel(const float* __restrict__ obj,
                   const float* __restrict__ deltas,
                   const float* __restrict__ anchors) {
    int task = blockIdx.x;
    int b = task / 5, lvl = task % 5;
    int nl = c_lvl_k[lvl];
    __shared__ unsigned long long skey[1024];
    __shared__ float4 s_box[1024];
    __shared__ unsigned char s_val[1024];

    int tid = threadIdx.x, lane = tid & 31, wid = tid >> 5;
    unsigned long long key = 0ULL;

    if (tid < nl) {
        int p = lvl * 1000 + tid;
        int t = b * K_TOTAL + p;
        int gi = d_topidx[t];

        float logit = obj[(size_t)b * A_TOTAL + gi];
        float4 dl = *(const float4*)&deltas[((size_t)b * A_TOTAL + gi) * 4];
        float4 an = *(const float4*)&anchors[(size_t)gi * 4];

        float wa = __fsub_rn(an.z, an.x), ha = __fsub_rn(an.w, an.y);
        float cxa = __fadd_rn(an.x, __fmul_rn(0.5f, wa));
        float cya = __fadd_rn(an.y, __fmul_rn(0.5f, ha));

        const float CLIPV = 4.135166556742356f;
        float dw = fminf(dl.z, CLIPV);
        float dh = fminf(dl.w, CLIPV);

        float cx = __fadd_rn(__fmul_rn(dl.x, wa), cxa);
        float cy = __fadd_rn(__fmul_rn(dl.y, ha), cya);
        float w  = __fmul_rn(expf(dw), wa);
        float h  = __fmul_rn(expf(dh), ha);

        float x1 = __fsub_rn(cx, __fmul_rn(0.5f, w));
        float y1 = __fsub_rn(cy, __fmul_rn(0.5f, h));
        float x2 = __fadd_rn(cx, __fmul_rn(0.5f, w));
        float y2 = __fadd_rn(cy, __fmul_rn(0.5f, h));

        x1 = fminf(fmaxf(x1, 0.0f), 800.0f);
        y1 = fminf(fmaxf(y1, 0.0f), 800.0f);
        x2 = fminf(fmaxf(x2, 0.0f), 800.0f);
        y2 = fminf(fmaxf(y2, 0.0f), 800.0f);

        float score = __fdiv_rn(1.0f, __fadd_rn(1.0f, expf(-logit)));
        bool valid = (__fsub_rn(x2, x1) >= 0.001f) &&
                     (__fsub_rn(y2, y1) >= 0.001f) &&
                     (score >= 0.0f);
        float ssel = valid ? score : __int_as_float(0xff800000);

        d_boxes[(size_t)t * 4 + 0] = x1;
        d_boxes[(size_t)t * 4 + 1] = y1;
        d_boxes[(size_t)t * 4 + 2] = x2;
        d_boxes[(size_t)t * 4 + 3] = y2;
        d_score[t] = score;
        s_box[tid] = make_float4(x1, y1, x2, y2);
        s_val[tid] = valid ? 1 : 0;
        unsigned u = xf32(ssel);
        key = ((unsigned long long)u << 32) |
              (unsigned long long)(0xFFFFFFFFu - (unsigned)p);
    }
    skey[tid] = key;
    __syncthreads();

    for (unsigned sz = 2; sz <= 1024; sz <<= 1) {
        for (unsigned j = sz >> 1; j; j >>= 1) {
            unsigned i = (unsigned)tid, l = i ^ j;
            if (l > i) {
                unsigned long long x = skey[i], y = skey[l];
                bool up = ((i & sz) == 0);
                if (up ? (x < y) : (x > y)) { skey[i] = y; skey[l] = x; }
            }
            __syncthreads();
        }
    }
    key = skey[tid];

    float4 ob = make_float4(0.f, 0.f, 0.f, 0.f);
    float ar = 0.f;
    unsigned char kp = 0;
    if (key != 0ULL) {
        int p = (int)(0xFFFFFFFFu - (unsigned)(key & 0xFFFFFFFFULL));
        int local = p - lvl * 1000;
        float4 bx = s_box[local];
        float off = (float)lvl * 1000.0f;
        ob.x = __fadd_rn(bx.x, off);
        ob.y = __fadd_rn(bx.y, off);
        ob.z = __fadd_rn(bx.z, off);
        ob.w = __fadd_rn(bx.w, off);
        ar = __fmul_rn(__fsub_rn(ob.z, ob.x), __fsub_rn(ob.w, ob.y));
        kp = s_val[local];
    }
    d_sbx[task * 1024 + tid] = ob;
    d_sar[task * 1024 + tid] = ar;
    d_skey[task * 1024 + tid] = key;
    unsigned bal = __ballot_sync(0xffffffffu, kp != 0);
    if (lane == 0) d_valmask[task * 32 + wid] = bal;
}

// ---------------------------------------------------------------------------
// K6: suppression bit-matrix, triangular tiles (ic:64, jc:256), 256 threads.
// Never-written words are zero-initialized device memory (index-static).
// ---------------------------------------------------------------------------
extern "C" __global__ void __launch_bounds__(256)
supmask_kernel() {
    int e = blockIdx.x, task = blockIdx.y;
    int lvl = task % 5;
    int jc = c_tile_jc[e], ic = c_tile_ic[e];
    if (lvl == 4 && (jc >= 2 || ic >= 8)) return;   // rows/cols beyond 507 dead

    int tid = threadIdx.x;
    int lane = tid & 31;
    int Jg = jc * 8 + (tid >> 5);
    int j = jc * 256 + tid;
    int maxj = jc * 256 + (tid >> 5) * 32 + 31;

    __shared__ float4 s_bx[64];
    __shared__ float  s_ar[64];
    if (tid < 64) {
        s_bx[tid] = d_sbx[task * 1024 + ic * 64 + tid];
        s_ar[tid] = d_sar[task * 1024 + ic * 64 + tid];
    }
    __syncthreads();

    float4 bj = d_sbx[task * 1024 + j];
    float arj = d_sar[task * 1024 + j];

    #pragma unroll 4
    for (int ii = 0; ii < 64; ++ii) {
        int i = ic * 64 + ii;
        if (maxj <= i) continue;            // warp-uniform, word stays 0
        float4 bi = s_bx[ii];
        float ai = s_ar[ii];
        bool sup = false;
        if (j > i) {
            float xx1 = fmaxf(bi.x, bj.x);
            float yy1 = fmaxf(bi.y, bj.y);
            float xx2 = fminf(bi.z, bj.z);
            float yy2 = fminf(bi.w, bj.w);
            float w = fmaxf(__fsub_rn(xx2, xx1), 0.0f);
            float h = fmaxf(__fsub_rn(yy2, yy1), 0.0f);
            float inter = __fmul_rn(w, h);
            float uni = __fsub_rn(__fadd_rn(ai, arj), inter);
            float r = __fmaf_rn(-0.7f, uni, inter);
            float m = __fmul_rn(uni, 3.0e-7f);
            if (fabsf(r) > m) sup = (r > 0.0f);
            else if (uni > 0.0f) sup = (__fdiv_rn(inter, uni) > 0.7f);
        }
        unsigned bal = __ballot_sync(0xffffffffu, sup);
        if (lane == 0) d_sup[(task * 1024 + i) * 32 + Jg] = bal;
    }
}

// ---------------------------------------------------------------------------
// K7: warp-serial greedy walk + compaction of kept keys per level.
// ---------------------------------------------------------------------------
extern "C" __global__ void __launch_bounds__(1024)
walk_kernel() {
    int task = blockIdx.x;
    extern __shared__ unsigned s_sup[];   // [1024][32]
    __shared__ unsigned s_aw[32];
    __shared__ int s_wsum[32], s_wbase[32];

    int tid = threadIdx.x, lane = tid & 31, wid = tid >> 5;

    for (int q = tid; q < 32768; q += 1024)
        s_sup[q] = d_sup[task * 32768 + q];
    __syncthreads();

    if (wid == 0) {
        unsigned alive = d_valmask[task * 32 + lane];
        #pragma unroll 1
        for (int c = 0; c < 32; ++c) {
            unsigned a = __shfl_sync(0xffffffffu, alive, c);
            if (a) {
                unsigned w[32];
                #pragma unroll
                for (int t = 0; t < 32; ++t)
                    w[t] = s_sup[(c * 32 + t) * 32 + c];
                #pragma unroll
                for (int t = 0; t < 32; ++t)
                    if (a & (1u << t)) a &= ~w[t];
                #pragma unroll
                for (int t = 0; t < 32; ++t)
                    if ((a >> t) & 1u) alive &= ~s_sup[(c * 32 + t) * 32 + lane];
            }
            if (lane == c) alive = a;
        }
        s_aw[lane] = alive;
    }
    __syncthreads();

    bool keep = (s_aw[wid] >> lane) & 1u;
    unsigned bal = __ballot_sync(0xffffffffu, keep);
    if (lane == 0) s_wsum[wid] = __popc(bal);
    __syncthreads();
    if (tid == 0) {
        int s = 0;
        for (int w2 = 0; w2 < 32; ++w2) { s_wbase[w2] = s; s += s_wsum[w2]; }
        d_lvl_cnt[task] = s;
    }
    __syncthreads();
    if (keep) {
        int slot = s_wbase[wid] + __popc(bal & ((1u << lane) - 1u));
        d_lvl_keys[task * 1024 + slot] = d_skey[task * 1024 + tid];
    }
}

// ---------------------------------------------------------------------------
// K8: per image, rank kept items across 5 sorted lists, write output.
// ---------------------------------------------------------------------------
extern "C" __global__ void __launch_bounds__(1024)
merge_kernel(float* __restrict__ out) {
    int b = blockIdx.x;
    __shared__ unsigned long long s_keys[5][1024];
    __shared__ int s_cnt[5];

    int tid = threadIdx.x;
    if (tid < 5) s_cnt[tid] = d_lvl_cnt[b * 5 + tid];
    __syncthreads();

    for (int i = tid; i < 5 * 1024; i += 1024) {
        int lvl = i >> 10, r = i & 1023;
        if (r < s_cnt[lvl])
            s_keys[lvl][r] = d_lvl_keys[(b * 5 + lvl) * 1024 + r];
    }
    __syncthreads();

    int total = s_cnt[0] + s_cnt[1] + s_cnt[2] + s_cnt[3] + s_cnt[4];

    for (int i = tid; i < 5 * 1024; i += 1024) {
        int lvl = i >> 10, r = i & 1023;
        if (r >= s_cnt[lvl]) continue;
        unsigned long long key = s_keys[lvl][r];
        int rank = r;
        #pragma unroll
        for (int o = 0; o < 5; ++o) {
            if (o == lvl) continue;
            int lo = 0, hi = s_cnt[o];
            while (lo < hi) {
                int mid = (lo + hi) >> 1;
                if (s_keys[o][mid] > key) lo = mid + 1; else hi = mid;
            }
            rank += lo;
        }
        if (rank < POST_NMS) {
            int p = (int)(0xFFFFFFFFu - (unsigned)(key & 0xFFFFFFFFULL));
            float4 bx = *(const float4*)&d_boxes[((size_t)b * K_TOTAL + p) * 4];
            float* o2 = out + ((size_t)b * POST_NMS + rank) * 5;
            o2[0] = bx.x; o2[1] = bx.y; o2[2] = bx.z; o2[3] = bx.w;
            o2[4] = d_score[b * K_TOTAL + p];
        }
    }
    if (tid < POST_NMS && tid >= total) {
        float* o2 = out + ((size_t)b * POST_NMS + tid) * 5;
        o2[0] = 0.f; o2[1] = 0.f; o2[2] = 0.f; o2[3] = 0.f; o2[4] = 0.f;
    }
}

// ---------------------------------------------------------------------------
extern "C" void kernel_launch(void* const* d_in, const int* in_sizes, int n_in,
                              void* d_out, int out_size) {
    const float* obj     = (const float*)d_in[0];
    const float* deltas  = (const float*)d_in[1];
    const float* anchors = (const float*)d_in[2];
    float* out = (float*)d_out;

    cudaFuncSetAttribute(hist_kernel, cudaFuncAttributeMaxDynamicSharedMemorySize,
                         HB * (int)sizeof(unsigned));
    cudaFuncSetAttribute(walk_kernel, cudaFuncAttributeMaxDynamicSharedMemorySize,
                         131072);

    zero_kernel<<<(NTASK * HB + 1023) / 1024, 1024>>>();
    hist_kernel<<<dim3(8, NTASK), 1024, HB * sizeof(unsigned)>>>(obj);
    pivot_kernel<<<NTASK, 1024>>>();
    select_kernel<<<dim3(8, NTASK), 1024>>>(obj);
    sortk_kernel<<<NTASK, 1024>>>();
    decode_sort_kernel<<<NTASK, 1024>>>(obj, deltas, anchors);
    supmask_kernel<<<dim3(40, NTASK), 256>>>();
    walk_kernel<<<NTASK, 1024, 131072>>>();
    merge_kernel<<<NB, 1024>>>(out);
}